// round 15
// baseline (speedup 1.0000x reference)
#include <cuda_runtime.h>

// y[i,o,n] = sum_{j,k} x[j,(o-1)%28,n+k-1]*W[i,j,0,k] + x[j,(o-2)%28,n+k-1]*W[i,j,1,k]
// x:(64,28,28) f32, W:(128,64,2,3) f32, y:(128,28,28) f32, zero-pad over n.
//
// ONE kernel. Block = 4 ch x 2 o-rows x 28 n; 4 warps, warp w owns j in [16w,16w+16).
// f32x2 pairs over CHANNELS (R14): one broadcast LDS.128 of ws4[j][m][c0..c3]
// feeds all 4 channels per tap. 128 thr, __launch_bounds__(128,4) -> 128-reg
// budget so ptxas can hoist/double-buffer LDS across the 29-cyc smem latency.
// Grid (32,14)=448 blocks, 4/SM allowed -> one wave. In-block smem reduce.

typedef unsigned long long u64;

static __device__ __forceinline__ u64 pk2(float a, float b) {
    u64 r; asm("mov.b64 %0, {%1, %2};" : "=l"(r) : "f"(a), "f"(b)); return r;
}
static __device__ __forceinline__ void up2(float& a, float& b, u64 v) {
    asm("mov.b64 {%0, %1}, %2;" : "=f"(a), "=f"(b) : "l"(v));
}
static __device__ __forceinline__ void fma2(u64& d, u64 a, u64 b) {
    asm("fma.rn.f32x2 %0, %1, %2, %0;" : "+l"(d) : "l"(a), "l"(b));
}
static __device__ __forceinline__ u64 lds64(unsigned sa) {
    u64 r; asm("ld.shared.b64 %0, [%1];" : "=l"(r) : "r"(sa)); return r;
}
static __device__ __forceinline__ void lds128_2x64(u64& a, u64& b, unsigned sa) {
    asm("ld.shared.v2.b64 {%0, %1}, [%2];" : "=l"(a), "=l"(b) : "r"(sa));
}

#define NJW 16  // j per warp
#define NW  4   // warps per block
#define ICB 4   // channels per block
// block output tile: ICB x 2 o-rows x 28 n = 224 floats

__global__ __launch_bounds__(128, 4)
void conv_one_kernel(const float* __restrict__ x,
                     const float* __restrict__ W,
                     float* __restrict__ out) {
    // x: 3 rows per j (global rows ob-2, ob-1, ob), padded: col n -> slot n+1,
    // slots 0 and 29..33 zeroed. Row stride 34 de-phases banks.
    __shared__ __align__(16) float xs[64][3][34];    // 26112 B
    // weights by tap: ws4[j][m][c] = W[ib+c][j][l][k], m = l*3+k. One LDS.128
    // per (j,m) broadcasts all 4 channels.
    __shared__ __align__(16) float ws4[64][6][4];    // 6144 B
    float* pred = &xs[0][0][0];  // reused after mainloop: [NW][224]

    const int tid = threadIdx.x;
    const int ib = blockIdx.x * ICB;   // 0..124
    const int ob = blockIdx.y * 2;     // 0..26

    // zero pad slots (0 and 29..33) per (j,row): 192 rows, 128 threads
    for (int i = tid; i < 64 * 3; i += 128) {
        int j = i / 3, rl = i - j * 3;
        float* r = &xs[j][rl][0];
        r[0] = 0.f; r[29] = 0.f; r[30] = 0.f; r[31] = 0.f; r[32] = 0.f; r[33] = 0.f;
    }
    // stage x: 64 j x 3 rows x 7 float4 = 1344 float4 loads, 11 rounds guarded
    #pragma unroll
    for (int q = 0; q < 11; q++) {
        int idx4 = tid + 128 * q;
        if (idx4 < 1344) {
            int j   = idx4 / 21;
            int rem = idx4 - j * 21;
            int rl  = rem / 7;
            int n4  = rem - rl * 7;
            int row = ob - 2 + rl;
            if (row < 0) row += 28;
            float4 v = *reinterpret_cast<const float4*>(x + j * 784 + row * 28 + 4 * n4);
            float* d = &xs[j][rl][1 + 4 * n4];
            d[0] = v.x; d[1] = v.y; d[2] = v.z; d[3] = v.w;
        }
    }
    // stage weights: 64 j x 6 m x 4 c = 1536 = 12*128 exactly
    #pragma unroll
    for (int q = 0; q < 12; q++) {
        int idx = tid + 128 * q;
        int j   = idx / 24;
        int rem = idx - j * 24;
        int m   = rem / 4;          // m = l*3 + k
        int c   = rem & 3;
        ws4[j][m][c] = W[(ib + c) * 384 + j * 6 + m];
    }
    __syncthreads();

    const int warp = tid >> 5;     // 0..3
    const int lane = tid & 31;
    const int ol = lane & 1;       // o-row within block
    const int ng = lane >> 1;      // 0..15; ng>=14 redundant (masked at store)
    const int n0 = 2 * ng;         // first output col of this thread's pair

    const unsigned xs_sa = (unsigned)__cvta_generic_to_shared(&xs[0][0][0]);
    const unsigned ws_sa = (unsigned)__cvta_generic_to_shared(&ws4[0][0][0]);

    // acc[p][n]: p=0 -> channels (c0,c1), p=1 -> (c2,c3); n = col n0+n
    u64 acc00 = 0ULL, acc10 = 0ULL, acc01 = 0ULL, acc11 = 0ULL;

    const int j0 = warp * NJW;
    #pragma unroll
    for (int t = 0; t < NJW; t++) {
        const int j = j0 + t;
        // out row o = ob+ol: row (o-1) -> rl = ol+1 (l=0 taps); row (o-2) -> rl = ol (l=1)
        const unsigned r1 = xs_sa + (unsigned)(((j * 3 + ol + 1) * 34 + n0) * 4);
        const unsigned r2 = xs_sa + (unsigned)(((j * 3 + ol) * 34 + n0) * 4);
        const unsigned wsa = ws_sa + (unsigned)(j * 96);  // 6 taps * 16B

        // all loads of this iteration issued up front (reg budget allows hoisting)
        u64 A0 = lds64(r1), A2 = lds64(r1 + 8);   // slots (n0,n0+1), (n0+2,n0+3)
        u64 B0 = lds64(r2), B2 = lds64(r2 + 8);
        u64 w0A, w0B, w1A, w1B, w2A, w2B, w3A, w3B, w4A, w4B, w5A, w5B;
        lds128_2x64(w0A, w0B, wsa);        // m=0 (l0,k0)
        lds128_2x64(w1A, w1B, wsa + 16);   // m=1 (l0,k1)
        lds128_2x64(w2A, w2B, wsa + 32);   // m=2 (l0,k2)
        lds128_2x64(w3A, w3B, wsa + 48);   // m=3 (l1,k0)
        lds128_2x64(w4A, w4B, wsa + 64);   // m=4 (l1,k1)
        lds128_2x64(w5A, w5B, wsa + 80);   // m=5 (l1,k2)

        float a0, a1, a2, a3, b0, b1, b2, b3;
        up2(a0, a1, A0); up2(a2, a3, A2);
        up2(b0, b1, B0); up2(b2, b3, B2);
        // lane-duplicated x taps
        u64 X0 = pk2(a0, a0), X1 = pk2(a1, a1), X2 = pk2(a2, a2), X3 = pk2(a3, a3);
        u64 Y0 = pk2(b0, b0), Y1 = pk2(b1, b1), Y2 = pk2(b2, b2), Y3 = pk2(b3, b3);

        // m=0: col n0 uses slot n0 (X0), col n0+1 uses X1
        fma2(acc00, X0, w0A); fma2(acc10, X0, w0B);
        fma2(acc01, X1, w0A); fma2(acc11, X1, w0B);
        // m=1: X1 / X2
        fma2(acc00, X1, w1A); fma2(acc10, X1, w1B);
        fma2(acc01, X2, w1A); fma2(acc11, X2, w1B);
        // m=2: X2 / X3
        fma2(acc00, X2, w2A); fma2(acc10, X2, w2B);
        fma2(acc01, X3, w2A); fma2(acc11, X3, w2B);
        // m=3: Y0 / Y1
        fma2(acc00, Y0, w3A); fma2(acc10, Y0, w3B);
        fma2(acc01, Y1, w3A); fma2(acc11, Y1, w3B);
        // m=4: Y1 / Y2
        fma2(acc00, Y1, w4A); fma2(acc10, Y1, w4B);
        fma2(acc01, Y2, w4A); fma2(acc11, Y2, w4B);
        // m=5: Y2 / Y3
        fma2(acc00, Y2, w5A); fma2(acc10, Y2, w5B);
        fma2(acc01, Y3, w5A); fma2(acc11, Y3, w5B);
    }

    __syncthreads();   // all xs reads complete; safe to overwrite with partials

    if (ng < 14) {
        // transpose channel-pairs back to per-channel col-pairs
        float c0n0, c1n0, c2n0, c3n0, c0n1, c1n1, c2n1, c3n1;
        up2(c0n0, c1n0, acc00); up2(c2n0, c3n0, acc10);
        up2(c0n1, c1n1, acc01); up2(c2n1, c3n1, acc11);
        float* pb = &pred[warp * 224 + ol * 28 + n0];
        *reinterpret_cast<float2*>(pb + 0 * 56) = make_float2(c0n0, c0n1);
        *reinterpret_cast<float2*>(pb + 1 * 56) = make_float2(c1n0, c1n1);
        *reinterpret_cast<float2*>(pb + 2 * 56) = make_float2(c2n0, c2n1);
        *reinterpret_cast<float2*>(pb + 3 * 56) = make_float2(c3n0, c3n1);
    }
    __syncthreads();

    #pragma unroll
    for (int i = tid; i < 224; i += 128) {
        float s = 0.f;
        #pragma unroll
        for (int w = 0; w < NW; w++) s += pred[w * 224 + i];  // stride 224%32==0: conflict-free
        int c   = i / 56;
        int rem = i - c * 56;
        int o2  = rem / 28;
        int n   = rem - o2 * 28;
        out[(ib + c) * 784 + (ob + o2) * 28 + n] = s;
    }
}

extern "C" void kernel_launch(void* const* d_in, const int* in_sizes, int n_in,
                              void* d_out, int out_size) {
    const float* x = (const float*)d_in[0];  // (1,64,28,28)  = 50176 f32
    const float* W = (const float*)d_in[1];  // (128,64,2,3) = 147456 f32
    float* out = (float*)d_out;              // (1,128,28,28) = 100352 f32

    dim3 grid(32, 14);  // (i-groups of 4, o-groups of 2) = 448 blocks, one wave
    conv_one_kernel<<<grid, 128>>>(x, W, out);
}